// round 10
// baseline (speedup 1.0000x reference)
#include <cuda_runtime.h>
#include <math.h>
#include <stdint.h>

#define TT 1024
#define DD 256
#define HH 256

// ---------------- persistent scratch ----------------
// packed (tf32-hi, tf32-lo) operands:
__device__ float2   g_Kp [TT*DD];
__device__ float2   g_Qp [TT*DD];
__device__ float2   g_Vp [TT*DD];
__device__ float2   g_Ap [TT*TT];
__device__ float2   g_Op [TT*HH];
__device__ float2   g_H1p[TT*HH];
__device__ float2   g_H2p[TT*HH];
__device__ float    g_skip[TT*HH];
__device__ float    g_H3 [TT*HH];
__device__ unsigned g_M  [TT*32];
__device__ float    g_den[TT], g_ksum[TT], g_qsum[TT];
__device__ unsigned g_Dm[2048*32], g_Sm[2048*32];
__device__ int      g_Dg[2048];

// ---------------- tf32 helpers (proven in R7/R8) ----------------
__device__ __forceinline__ float tf32r(float f) {
    unsigned u; asm("cvt.rna.tf32.f32 %0,%1;" : "=r"(u) : "f"(f));
    return __uint_as_float(u);
}
__device__ __forceinline__ float2 splitf(float f) {
    float h = tf32r(f);
    return make_float2(h, tf32r(f - h));
}
__device__ __forceinline__ void mma_tf32(float d[4], const float a[4], const float b[2]) {
    asm volatile(
        "mma.sync.aligned.m16n8k8.row.col.f32.tf32.tf32.f32 "
        "{%0,%1,%2,%3},{%4,%5,%6,%7},{%8,%9},{%0,%1,%2,%3};"
        : "+f"(d[0]), "+f"(d[1]), "+f"(d[2]), "+f"(d[3])
        : "r"(__float_as_uint(a[0])), "r"(__float_as_uint(a[1])),
          "r"(__float_as_uint(a[2])), "r"(__float_as_uint(a[3])),
          "r"(__float_as_uint(b[0])), "r"(__float_as_uint(b[1])));
}
#define SWK(k, c) ((c) ^ (((k) & 3) << 3))

// ---------------- 16-k stage compute: warp tile 32x32 ----------------
template<int WN>
__device__ __forceinline__ void stage_compute(
    const float2 (*sA)[64], const float2 (*sB)[32*WN],
    float acc[2][4][4], int wm, int wn, int g, int t4)
{
    const int sw = t4 << 3;
#pragma unroll
    for (int kb = 0; kb < 16; kb += 8) {
        float ah[2][4], al[2][4];
#pragma unroll
        for (int mt = 0; mt < 2; mt++) {
            int r0 = wm*32 + mt*16 + g;
            float2 a0 = sA[kb+t4  ][ r0      ^ sw];
            float2 a1 = sA[kb+t4  ][(r0 + 8) ^ sw];
            float2 a2 = sA[kb+t4+4][ r0      ^ sw];
            float2 a3 = sA[kb+t4+4][(r0 + 8) ^ sw];
            ah[mt][0]=a0.x; ah[mt][1]=a1.x; ah[mt][2]=a2.x; ah[mt][3]=a3.x;
            al[mt][0]=a0.y; al[mt][1]=a1.y; al[mt][2]=a2.y; al[mt][3]=a3.y;
        }
#pragma unroll
        for (int nt = 0; nt < 4; nt++) {
            int c = wn*32 + nt*8 + g;
            float2 b0 = sB[kb+t4  ][c ^ sw];
            float2 b1 = sB[kb+t4+4][c ^ sw];
            float bh[2] = {b0.x, b1.x};
            float bl[2] = {b0.y, b1.y};
#pragma unroll
            for (int mt = 0; mt < 2; mt++) {
                mma_tf32(acc[mt][nt], ah[mt], bh);   // hi*hi
                mma_tf32(acc[mt][nt], ah[mt], bl);   // hi*lo
                mma_tf32(acc[mt][nt], al[mt], bh);   // lo*hi
            }
        }
    }
}

// ---------------- unified GEMM core ----------------
// block tile 64 x (32*WN), 2 x WN warps. A: 64 rows k-contig (f32 or packed).
// BMODE: 0 = f32 TT (32*WN rows) | 1 = packed TT | 2 = packed TN (k rows, n-contig)
template<int WN, bool AF32, int BMODE>
__device__ __forceinline__ void tc_gemm(
    const float* __restrict__ Af, const float2* __restrict__ Ap, int lda, int m0,
    const float* __restrict__ Bf, const float2* __restrict__ Bp, int ldb, int n0,
    int K, float acc[2][4][4],
    float2 (*sA)[64], float2 (*sB)[32*WN])
{
    constexpr int T  = 64*WN;
    constexpr int NA = AF32 ? (256/T) : (512/T);
    constexpr int NB = (BMODE == 0) ? 2 : 4;
    const int tid = threadIdx.x, lane = tid & 31, warp = tid >> 5;
    const int wm = warp / WN, wn = warp % WN;
    const int g = lane >> 2, t4 = lane & 3;

    float4 fa[NA], fb[NB];

    auto FETCH_A = [&](int k0) {
#pragma unroll
        for (int i = 0; i < NA; i++) {
            int e = tid + i*T;
            if constexpr (AF32) {
                int row = e >> 2, k4 = (e & 3) << 2;
                fa[i] = *(const float4*)&Af[(size_t)(m0+row)*lda + k0 + k4];
            } else {
                int row = e >> 3, k2 = (e & 7) << 1;
                fa[i] = *(const float4*)&Ap[(size_t)(m0+row)*lda + k0 + k2];
            }
        }
    };
    auto STORE_A = [&](int bs) {
#pragma unroll
        for (int i = 0; i < NA; i++) {
            int e = tid + i*T;
            if constexpr (AF32) {
                int row = e >> 2, k4 = (e & 3) << 2;
                const float* f = (const float*)&fa[i];
#pragma unroll
                for (int j = 0; j < 4; j++)
                    sA[bs + k4 + j][SWK(k4+j, row)] = splitf(f[j]);
            } else {
                int row = e >> 3, k2 = (e & 7) << 1;
                sA[bs + k2    ][SWK(k2,   row)] = make_float2(fa[i].x, fa[i].y);
                sA[bs + k2 + 1][SWK(k2+1, row)] = make_float2(fa[i].z, fa[i].w);
            }
        }
    };
    auto FETCH_B = [&](int k0) {
#pragma unroll
        for (int i = 0; i < NB; i++) {
            int e = tid + i*T;
            if constexpr (BMODE == 0) {
                int row = e >> 2, k4 = (e & 3) << 2;
                fb[i] = *(const float4*)&Bf[(size_t)(n0+row)*ldb + k0 + k4];
            } else if constexpr (BMODE == 1) {
                int row = e >> 3, k2 = (e & 7) << 1;
                fb[i] = *(const float4*)&Bp[(size_t)(n0+row)*ldb + k0 + k2];
            } else {
                int k = e / (16*WN), n2 = (e % (16*WN)) << 1;
                fb[i] = *(const float4*)&Bp[(size_t)(k0+k)*ldb + n0 + n2];
            }
        }
    };
    auto STORE_B = [&](int bs) {
#pragma unroll
        for (int i = 0; i < NB; i++) {
            int e = tid + i*T;
            if constexpr (BMODE == 0) {
                int row = e >> 2, k4 = (e & 3) << 2;
                const float* f = (const float*)&fb[i];
#pragma unroll
                for (int j = 0; j < 4; j++)
                    sB[bs + k4 + j][SWK(k4+j, row)] = splitf(f[j]);
            } else if constexpr (BMODE == 1) {
                int row = e >> 3, k2 = (e & 7) << 1;
                sB[bs + k2    ][SWK(k2,   row)] = make_float2(fb[i].x, fb[i].y);
                sB[bs + k2 + 1][SWK(k2+1, row)] = make_float2(fb[i].z, fb[i].w);
            } else {
                int k = e / (16*WN), n2 = (e % (16*WN)) << 1;
                sB[bs + k][SWK(k, n2    )] = make_float2(fb[i].x, fb[i].y);
                sB[bs + k][SWK(k, n2 + 1)] = make_float2(fb[i].z, fb[i].w);
            }
        }
    };

    FETCH_A(0); FETCH_B(0);
    STORE_A(0); STORE_B(0);
    __syncthreads();
    int buf = 0;
    for (int k0 = 16; k0 <= K; k0 += 16) {
        bool more = (k0 < K);
        if (more) { FETCH_A(k0); FETCH_B(k0); }
        stage_compute<WN>(sA + buf*16, sB + buf*16, acc, wm, wn, g, t4);
        if (more) {
            STORE_A((buf^1)*16); STORE_B((buf^1)*16);
            __syncthreads();
            buf ^= 1;
        }
    }
}

// ---------------------------------------------------------------------------
// Exact simulation of jax.lax.associative_scan bracketing on 1024-bit masks.
// ---------------------------------------------------------------------------
__global__ void scan_mask_kernel(const int* __restrict__ start, const int* __restrict__ done) {
    const int n[11]   = {1025,512,256,128,64,32,16,8,4,2,1};
    const int off[11] = {0,1025,1537,1793,1921,1985,2017,2033,2041,2045,2047};
    int tid = threadIdx.x;

    if (tid < 1024) { g_ksum[tid] = 0.f; g_qsum[tid] = 0.f; }

    for (int idx = tid; idx < 1025*32; idx += blockDim.x) {
        int i = idx >> 5, w = idx & 31;
        unsigned m = 0;
        if (i > 0 && ((i-1) >> 5) == w) m = 1u << ((i-1) & 31);
        g_Dm[idx] = m;
        if (w == 0) g_Dg[i] = (start[i] ? 1 : 0) | (done[i] ? 2 : 0);
    }
    __syncthreads();

    for (int d = 0; d < 10; d++) {
        int nn = n[d+1];
        int src = off[d], dst = off[d+1];
        for (int idx = tid; idx < nn*32; idx += blockDim.x) {
            int i = idx >> 5, w = idx & 31;
            int gb = g_Dg[src + 2*i + 1];
            unsigned m = 0;
            if (gb & 1) m |= g_Dm[(src + 2*i    )*32 + w];
            if (gb & 2) m |= g_Dm[(src + 2*i + 1)*32 + w];
            g_Dm[(dst + i)*32 + w] = m;
            if (w == 0) g_Dg[dst + i] = gb;
        }
        __syncthreads();
    }

    for (int w = tid; w < 32; w += blockDim.x)
        g_Sm[off[10]*32 + w] = g_Dm[off[10]*32 + w];
    __syncthreads();

    for (int d = 9; d >= 0; d--) {
        int nd = n[d];
        int src = off[d], o = off[d+1];
        for (int idx = tid; idx < nd*32; idx += blockDim.x) {
            int pos = idx >> 5, w = idx & 31;
            unsigned m;
            if (pos == 0) {
                m = g_Dm[src*32 + w];
            } else if (pos & 1) {
                m = g_Sm[(o + (pos >> 1))*32 + w];
            } else {
                int i = (pos >> 1) - 1;
                int gb = g_Dg[src + pos];
                m = 0;
                if (gb & 1) m |= g_Sm[(o + i)*32 + w];
                if (gb & 2) m |= g_Dm[(src + pos)*32 + w];
            }
            g_Sm[(src + pos)*32 + w] = m;
        }
        __syncthreads();
    }

    for (int idx = tid; idx < 1024*32; idx += blockDim.x) {
        int t = idx >> 5, w = idx & 31;
        g_M[idx] = g_Sm[(t + 1)*32 + w];
    }
}

// ---------------------------------------------------------------------------
// Projections: k/q (elu, packed + rowsums), v (packed), skip (f32)
// grid (8 = 4 wsel x 2 coltile, 16), 256 threads, block 64x128
// ---------------------------------------------------------------------------
__global__ void __launch_bounds__(256) proj_kernel(
    const float* __restrict__ X,
    const float* __restrict__ Wk, const float* __restrict__ Wq,
    const float* __restrict__ Wv, const float* __restrict__ Ws,
    const float* __restrict__ bskip)
{
    __shared__ float2 sA[32][64];
    __shared__ float2 sB[32][128];
    int bx = blockIdx.x, by = blockIdx.y;
    int wsel = bx >> 1, n0 = (bx & 1) * 128, m0 = by * 64;
    const float* W = (wsel == 0) ? Wk : (wsel == 1) ? Wq : (wsel == 2) ? Wv : Ws;

    float acc[2][4][4] = {};
    tc_gemm<4, true, 0>(X, nullptr, DD, m0, W, nullptr, DD, n0, DD, acc, sA, sB);

    int tid = threadIdx.x, lane = tid & 31, warp = tid >> 5;
    int wm = warp >> 2, wn = warp & 3, g = lane >> 2, t4 = lane & 3;

    float rs[4] = {0.f, 0.f, 0.f, 0.f};  // [mt*2 + h]
#pragma unroll
    for (int mt = 0; mt < 2; mt++)
#pragma unroll
    for (int nt = 0; nt < 4; nt++)
#pragma unroll
    for (int e = 0; e < 4; e++) {
        int r = m0 + wm*32 + mt*16 + g + (e >> 1) * 8;
        int c = n0 + wn*32 + nt*8 + t4*2 + (e & 1);
        float v = acc[mt][nt][e];
        if (wsel < 2) {
            v = (v > 0.f) ? v : expm1f(v);
            ((wsel == 0) ? g_Kp : g_Qp)[(size_t)r * DD + c] = splitf(v);
            rs[mt*2 + (e >> 1)] += v;
        } else if (wsel == 2) {
            g_Vp[(size_t)r * DD + c] = splitf(v);
        } else {
            g_skip[(size_t)r * HH + c] = v + bskip[c];
        }
    }
    if (wsel < 2) {
        __syncthreads();
        float* red = (float*)sA;   // 64 x 17, fits in sA (8192 floats)
#pragma unroll
        for (int mt = 0; mt < 2; mt++)
#pragma unroll
        for (int h = 0; h < 2; h++)
            red[(wm*32 + mt*16 + g + h*8) * 17 + wn*4 + t4] = rs[mt*2 + h];
        __syncthreads();
        if (tid < 64) {
            float s = 0.f;
#pragma unroll
            for (int x = 0; x < 16; x++) s += red[tid * 17 + x];
            atomicAdd((wsel == 0) ? &g_ksum[m0 + tid] : &g_qsum[m0 + tid], s);
        }
    }
}

// ---------------------------------------------------------------------------
// denom[t] = qsum[t] * sum_j mask(t,j)*ksum[j]
// ---------------------------------------------------------------------------
__global__ void denom_kernel() {
    __shared__ float ks[1024];
    int tid = threadIdx.x;
    for (int i = tid; i < 1024; i += 256) ks[i] = g_ksum[i];
    __syncthreads();
    int row  = blockIdx.x * 8 + (tid >> 5);
    int lane = tid & 31;
    unsigned bits = g_M[row * 32 + lane];
    float s = 0.f;
    while (bits) {
        int b = __ffs(bits) - 1;
        bits &= bits - 1;
        s += ks[lane * 32 + b];
    }
#pragma unroll
    for (int o = 16; o > 0; o >>= 1) s += __shfl_xor_sync(0xffffffffu, s, o);
    if (lane == 0) g_den[row] = s * g_qsum[row];
}

// ---------------------------------------------------------------------------
// Masked scores: 72 lower-tri tiles of 64 rows x 128 cols, 256 threads.
// ---------------------------------------------------------------------------
__global__ void __launch_bounds__(256) scores_kernel() {
    int l = blockIdx.x;
    int bt = 0, base = 0;
    while (base + (bt >> 1) + 1 <= l) { base += (bt >> 1) + 1; bt++; }
    int bi = l - base;

    __shared__ float2 sA[32][64];
    __shared__ float2 sB[32][128];
    float acc[2][4][4] = {};
    tc_gemm<4, false, 1>(nullptr, g_Qp, DD, bt * 64,
                         nullptr, g_Kp, DD, bi * 128, DD, acc, sA, sB);

    int tid = threadIdx.x, lane = tid & 31, warp = tid >> 5;
    int wm = warp >> 2, wn = warp & 3, g = lane >> 2, t4 = lane & 3;
#pragma unroll
    for (int mt = 0; mt < 2; mt++)
#pragma unroll
    for (int nt = 0; nt < 4; nt++)
#pragma unroll
    for (int e = 0; e < 4; e++) {
        int r  = bt*64 + wm*32 + mt*16 + g + (e >> 1) * 8;
        int ki = bi*128 + wn*32 + nt*8 + t4*2 + (e & 1);
        unsigned bit = (g_M[r * 32 + (ki >> 5)] >> (ki & 31)) & 1u;
        g_Ap[(size_t)r * TT + ki] = splitf(bit ? acc[mt][nt][e] : 0.f);
    }
}

// ---------------------------------------------------------------------------
// numer = A @ V (K truncated at diagonal), / clipped denom.
// grid (4, 16), 128 threads, block 64x64.
// ---------------------------------------------------------------------------
__global__ void __launch_bounds__(128) numer_kernel() {
    int bn = blockIdx.x, bt = blockIdx.y;
    __shared__ float2 sA[32][64];
    __shared__ float2 sB[32][64];
    float acc[2][4][4] = {};
    tc_gemm<2, false, 2>(nullptr, g_Ap, TT, bt * 64,
                         nullptr, g_Vp, DD, bn * 64, (bt + 1) * 64, acc, sA, sB);

    int tid = threadIdx.x, lane = tid & 31, warp = tid >> 5;
    int wm = warp >> 1, wn = warp & 1, g = lane >> 2, t4 = lane & 3;
#pragma unroll
    for (int mt = 0; mt < 2; mt++)
#pragma unroll
    for (int nt = 0; nt < 4; nt++)
#pragma unroll
    for (int e = 0; e < 4; e++) {
        int r = bt*64 + wm*32 + mt*16 + g + (e >> 1) * 8;
        int c = bn*64 + wn*32 + nt*8 + t4*2 + (e & 1);
        float inv = 1.f / fmaxf(g_den[r], 1e-5f);
        g_Op[(size_t)r * HH + c] = splitf(acc[mt][nt][e] * inv);
    }
}

// ---------------------------------------------------------------------------
// MLP GEMMs: grid (4, 16), 128 threads, block 64x64.
// ---------------------------------------------------------------------------
__device__ __forceinline__ float mishf(float v) {
    float sp = (v > 20.f) ? v : log1pf(expf(v));
    return v * tanhf(sp);
}

template <int MODE>
__global__ void __launch_bounds__(128) mlp_kernel(const float* __restrict__ W,
                                                  const float* __restrict__ bias) {
    int bn = blockIdx.x, bm = blockIdx.y;
    __shared__ float2 sA[32][64];
    __shared__ float2 sB[32][64];
    const float2* Ap = (MODE == 0) ? g_Op : (MODE == 1) ? g_H1p : g_H2p;
    float acc[2][4][4] = {};
    tc_gemm<2, false, 0>(nullptr, Ap, HH, bm * 64,
                         W, nullptr, HH, bn * 64, HH, acc, sA, sB);

    int tid = threadIdx.x, lane = tid & 31, warp = tid >> 5;
    int wm = warp >> 1, wn = warp & 1, g = lane >> 2, t4 = lane & 3;
#pragma unroll
    for (int mt = 0; mt < 2; mt++)
#pragma unroll
    for (int nt = 0; nt < 4; nt++)
#pragma unroll
    for (int e = 0; e < 4; e++) {
        int r = bm*64 + wm*32 + mt*16 + g + (e >> 1) * 8;
        int c = bn*64 + wn*32 + nt*8 + t4*2 + (e & 1);
        float v = acc[mt][nt][e] + bias[c];
        if (MODE < 2) {
            v = mishf(v);
            ((MODE == 0) ? g_H1p : g_H2p)[(size_t)r * HH + c] = splitf(v);
        } else {
            g_H3[(size_t)r * HH + c] = v + g_skip[(size_t)r * HH + c];
        }
    }
}

// ---------------------------------------------------------------------------
// Per-row LayerNorm
// ---------------------------------------------------------------------------
__global__ void ln_kernel(const float* __restrict__ w, const float* __restrict__ b,
                          float* __restrict__ out) {
    int row = blockIdx.x, tid = threadIdx.x;
    float v = g_H3[(size_t)row * HH + tid];
    __shared__ float sh[8];
    float s = v;
#pragma unroll
    for (int o = 16; o > 0; o >>= 1) s += __shfl_xor_sync(0xffffffffu, s, o);
    if ((tid & 31) == 0) sh[tid >> 5] = s;
    __syncthreads();
    float tot = 0.f;
#pragma unroll
    for (int i = 0; i < 8; i++) tot += sh[i];
    float mean = tot * (1.f / 256.f);
    float d = v - mean;
    float s2 = d * d;
#pragma unroll
    for (int o = 16; o > 0; o >>= 1) s2 += __shfl_xor_sync(0xffffffffu, s2, o);
    __syncthreads();
    if ((tid & 31) == 0) sh[tid >> 5] = s2;
    __syncthreads();
    float tot2 = 0.f;
#pragma unroll
    for (int i = 0; i < 8; i++) tot2 += sh[i];
    float var = tot2 * (1.f / 256.f);
    out[(size_t)row * HH + tid] = d * rsqrtf(var + 1e-5f) * w[tid] + b[tid];
}

// ---------------------------------------------------------------------------
extern "C" void kernel_launch(void* const* d_in, const int* in_sizes, int n_in,
                              void* d_out, int out_size) {
    const float* x     = (const float*)d_in[0];
    const int*   start = (const int*)d_in[3];
    const int*   done  = (const int*)d_in[4];
    const float* Wk = (const float*)d_in[5];
    const float* Wq = (const float*)d_in[6];
    const float* Wv = (const float*)d_in[7];
    const float* Ws = (const float*)d_in[8];
    const float* bskip = (const float*)d_in[9];
    const float* W1 = (const float*)d_in[10];
    const float* b1 = (const float*)d_in[11];
    const float* W2 = (const float*)d_in[12];
    const float* b2 = (const float*)d_in[13];
    const float* W3 = (const float*)d_in[14];
    const float* b3 = (const float*)d_in[15];
    const float* lnw = (const float*)d_in[16];
    const float* lnb = (const float*)d_in[17];
    float* out = (float*)d_out;

    scan_mask_kernel<<<1, 1024>>>(start, done);
    proj_kernel<<<dim3(8, 16), 256>>>(x, Wk, Wq, Wv, Ws, bskip);
    denom_kernel<<<128, 256>>>();
    scores_kernel<<<72, 256>>>();
    numer_kernel<<<dim3(4, 16), 128>>>();
    mlp_kernel<0><<<dim3(4, 16), 128>>>(W1, b1);
    mlp_kernel<1><<<dim3(4, 16), 128>>>(W2, b2);
    mlp_kernel<2><<<dim3(4, 16), 128>>>(W3, b3);
    ln_kernel<<<1024, 256>>>(lnw, lnb, out);
}

// round 11
// speedup vs baseline: 2.3671x; 2.3671x over previous
#include <cuda_runtime.h>
#include <math.h>

#define TT   1024
#define DD   256
#define HH   256
#define LDP  1024

// Scratch (static device globals; no allocation)
__device__ float    g_P[TT*LDP];   // cols [0,256)=k(elu) [256,512)=q(elu) [512,768)=v [768,1024)=skip
__device__ float    g_A[TT*TT];    // masked scores (lower-tri region valid)
__device__ float    g_O[TT*HH];
__device__ float    g_H1[TT*HH];
__device__ float    g_H2[TT*HH];
__device__ float    g_H3[TT*HH];
__device__ unsigned g_M[TT*32];
__device__ float    g_den[TT];
__device__ float    g_ksum[TT], g_qsum[TT];
__device__ unsigned g_Dm[2048*32];
__device__ unsigned g_Sm[2048*32];
__device__ int      g_Dg[2048];

// ---------------------------------------------------------------------------
// Exact simulation of jax.lax.associative_scan bracketing on 1024-bit masks.
// ---------------------------------------------------------------------------
__global__ void scan_mask_kernel(const int* __restrict__ start, const int* __restrict__ done) {
    const int n[11]   = {1025,512,256,128,64,32,16,8,4,2,1};
    const int off[11] = {0,1025,1537,1793,1921,1985,2017,2033,2041,2045,2047};
    int tid = threadIdx.x;

    if (tid < 1024) { g_ksum[tid] = 0.f; g_qsum[tid] = 0.f; }

    for (int idx = tid; idx < 1025*32; idx += blockDim.x) {
        int i = idx >> 5, w = idx & 31;
        unsigned m = 0;
        if (i > 0 && ((i-1) >> 5) == w) m = 1u << ((i-1) & 31);
        g_Dm[idx] = m;
        if (w == 0) g_Dg[i] = (start[i] ? 1 : 0) | (done[i] ? 2 : 0);
    }
    __syncthreads();

    for (int d = 0; d < 10; d++) {
        int nn = n[d+1];
        int src = off[d], dst = off[d+1];
        for (int idx = tid; idx < nn*32; idx += blockDim.x) {
            int i = idx >> 5, w = idx & 31;
            int gb = g_Dg[src + 2*i + 1];
            unsigned m = 0;
            if (gb & 1) m |= g_Dm[(src + 2*i    )*32 + w];
            if (gb & 2) m |= g_Dm[(src + 2*i + 1)*32 + w];
            g_Dm[(dst + i)*32 + w] = m;
            if (w == 0) g_Dg[dst + i] = gb;
        }
        __syncthreads();
    }

    for (int w = tid; w < 32; w += blockDim.x)
        g_Sm[off[10]*32 + w] = g_Dm[off[10]*32 + w];
    __syncthreads();

    for (int d = 9; d >= 0; d--) {
        int nd = n[d];
        int src = off[d], o = off[d+1];
        for (int idx = tid; idx < nd*32; idx += blockDim.x) {
            int pos = idx >> 5, w = idx & 31;
            unsigned m;
            if (pos == 0) {
                m = g_Dm[src*32 + w];
            } else if (pos & 1) {
                m = g_Sm[(o + (pos >> 1))*32 + w];
            } else {
                int i = (pos >> 1) - 1;
                int gb = g_Dg[src + pos];
                m = 0;
                if (gb & 1) m |= g_Sm[(o + i)*32 + w];
                if (gb & 2) m |= g_Dm[(src + pos)*32 + w];
            }
            g_Sm[(src + pos)*32 + w] = m;
        }
        __syncthreads();
    }

    for (int idx = tid; idx < 1024*32; idx += blockDim.x) {
        int t = idx >> 5, w = idx & 31;
        g_M[idx] = g_Sm[(t + 1)*32 + w];
    }
}

// ---------------------------------------------------------------------------
// fp32 GEMM cores: 128 threads, 32-row tiles, register double-buffered.
// ---------------------------------------------------------------------------
__device__ __forceinline__ void microfma44(float acc[4][4], float4 a, float4 b) {
    acc[0][0] += a.x*b.x; acc[0][1] += a.x*b.y; acc[0][2] += a.x*b.z; acc[0][3] += a.x*b.w;
    acc[1][0] += a.y*b.x; acc[1][1] += a.y*b.y; acc[1][2] += a.y*b.z; acc[1][3] += a.y*b.w;
    acc[2][0] += a.z*b.x; acc[2][1] += a.z*b.y; acc[2][2] += a.z*b.z; acc[2][3] += a.z*b.w;
    acc[3][0] += a.w*b.x; acc[3][1] += a.w*b.y; acc[3][2] += a.w*b.z; acc[3][3] += a.w*b.w;
}
__device__ __forceinline__ void microfma42(float acc[4][2], float4 a, float2 b) {
    acc[0][0] += a.x*b.x; acc[0][1] += a.x*b.y;
    acc[1][0] += a.y*b.x; acc[1][1] += a.y*b.y;
    acc[2][0] += a.z*b.x; acc[2][1] += a.z*b.y;
    acc[3][0] += a.w*b.x; acc[3][1] += a.w*b.y;
}

// C[32x64] = A[32xK] * B[64xK]^T  (both k-contiguous rows). 128 threads.
__device__ __forceinline__ void gemm_T3264(
    const float* __restrict__ A, int lda, int m0,
    const float* __restrict__ B, int ldb, int n0,
    int K, float acc[4][4],
    float (*As)[16][32], float (*Bs)[16][64],
    int tid, int tx, int ty)
{
    int rowA = tid >> 2, c4A = (tid & 3) << 2;   // 32 rows x 1 float4
    int rowB = tid >> 1, c8B = (tid & 1) << 3;   // 64 rows x 2 float4
    const float* pA = A + (size_t)(m0 + rowA) * lda + c4A;
    const float* pB = B + (size_t)(n0 + rowB) * ldb + c8B;
    float4 av = *(const float4*)pA;
    float4 bv0 = *(const float4*)pB;
    float4 bv1 = *(const float4*)(pB + 4);
    int buf = 0;
    As[0][c4A+0][rowA]=av.x; As[0][c4A+1][rowA]=av.y; As[0][c4A+2][rowA]=av.z; As[0][c4A+3][rowA]=av.w;
    Bs[0][c8B+0][rowB]=bv0.x; Bs[0][c8B+1][rowB]=bv0.y; Bs[0][c8B+2][rowB]=bv0.z; Bs[0][c8B+3][rowB]=bv0.w;
    Bs[0][c8B+4][rowB]=bv1.x; Bs[0][c8B+5][rowB]=bv1.y; Bs[0][c8B+6][rowB]=bv1.z; Bs[0][c8B+7][rowB]=bv1.w;
    __syncthreads();
    for (int k0 = 16; k0 <= K; k0 += 16) {
        bool more = (k0 < K);
        if (more) {
            av  = *(const float4*)(pA + k0);
            bv0 = *(const float4*)(pB + k0);
            bv1 = *(const float4*)(pB + k0 + 4);
        }
        float4 a_cur = *(const float4*)&As[buf][0][ty*4];
        float4 b_cur = *(const float4*)&Bs[buf][0][tx*4];
#pragma unroll
        for (int kk = 0; kk < 16; kk++) {
            float4 a_nxt = a_cur, b_nxt = b_cur;
            if (kk < 15) {
                a_nxt = *(const float4*)&As[buf][kk+1][ty*4];
                b_nxt = *(const float4*)&Bs[buf][kk+1][tx*4];
            }
            microfma44(acc, a_cur, b_cur);
            a_cur = a_nxt; b_cur = b_nxt;
        }
        if (more) {
            int nb = buf ^ 1;
            As[nb][c4A+0][rowA]=av.x; As[nb][c4A+1][rowA]=av.y; As[nb][c4A+2][rowA]=av.z; As[nb][c4A+3][rowA]=av.w;
            Bs[nb][c8B+0][rowB]=bv0.x; Bs[nb][c8B+1][rowB]=bv0.y; Bs[nb][c8B+2][rowB]=bv0.z; Bs[nb][c8B+3][rowB]=bv0.w;
            Bs[nb][c8B+4][rowB]=bv1.x; Bs[nb][c8B+5][rowB]=bv1.y; Bs[nb][c8B+6][rowB]=bv1.z; Bs[nb][c8B+7][rowB]=bv1.w;
            __syncthreads();
            buf = nb;
        }
    }
}

// C[32x32] = A[32xK] * B[32xK]^T  (TT) — 128 threads, 4x2 microtile.
__device__ __forceinline__ void gemm_T3232(
    const float* __restrict__ A, int lda, int m0,
    const float* __restrict__ B, int ldb, int n0,
    int K, float acc[4][2],
    float (*As)[16][32], float (*Bs)[16][32],
    int tid, int tx, int ty)
{
    int rowA = tid >> 2, c4 = (tid & 3) << 2;
    const float* pA = A + (size_t)(m0 + rowA) * lda + c4;
    const float* pB = B + (size_t)(n0 + rowA) * ldb + c4;
    float4 av = *(const float4*)pA;
    float4 bv = *(const float4*)pB;
    int buf = 0;
    As[0][c4+0][rowA]=av.x; As[0][c4+1][rowA]=av.y; As[0][c4+2][rowA]=av.z; As[0][c4+3][rowA]=av.w;
    Bs[0][c4+0][rowA]=bv.x; Bs[0][c4+1][rowA]=bv.y; Bs[0][c4+2][rowA]=bv.z; Bs[0][c4+3][rowA]=bv.w;
    __syncthreads();
    for (int k0 = 16; k0 <= K; k0 += 16) {
        bool more = (k0 < K);
        if (more) { av = *(const float4*)(pA + k0); bv = *(const float4*)(pB + k0); }
        float4 a_cur = *(const float4*)&As[buf][0][ty*4];
        float2 b_cur = *(const float2*)&Bs[buf][0][tx*2];
#pragma unroll
        for (int kk = 0; kk < 16; kk++) {
            float4 a_nxt = a_cur; float2 b_nxt = b_cur;
            if (kk < 15) {
                a_nxt = *(const float4*)&As[buf][kk+1][ty*4];
                b_nxt = *(const float2*)&Bs[buf][kk+1][tx*2];
            }
            microfma42(acc, a_cur, b_cur);
            a_cur = a_nxt; b_cur = b_nxt;
        }
        if (more) {
            int nb = buf ^ 1;
            As[nb][c4+0][rowA]=av.x; As[nb][c4+1][rowA]=av.y; As[nb][c4+2][rowA]=av.z; As[nb][c4+3][rowA]=av.w;
            Bs[nb][c4+0][rowA]=bv.x; Bs[nb][c4+1][rowA]=bv.y; Bs[nb][c4+2][rowA]=bv.z; Bs[nb][c4+3][rowA]=bv.w;
            __syncthreads();
            buf = nb;
        }
    }
}

// C[32x32] = A[32xK] * B[Kx32]  (TN, B n-contiguous) — 128 threads, 4x2.
__device__ __forceinline__ void gemm_N3232(
    const float* __restrict__ A, int lda, int m0,
    const float* __restrict__ B, int ldb, int n0,
    int K, float acc[4][2],
    float (*As)[16][32], float (*Bs)[16][32],
    int tid, int tx, int ty)
{
    int rowA = tid >> 2, c4A = (tid & 3) << 2;
    int kB = tid >> 3, cB = (tid & 7) << 2;
    const float* pA = A + (size_t)(m0 + rowA) * lda + c4A;
    const float* pB = B + (size_t)kB * ldb + n0 + cB;
    float4 av = *(const float4*)pA;
    float4 bv = *(const float4*)pB;
    int buf = 0;
    As[0][c4A+0][rowA]=av.x; As[0][c4A+1][rowA]=av.y; As[0][c4A+2][rowA]=av.z; As[0][c4A+3][rowA]=av.w;
    *(float4*)&Bs[0][kB][cB] = bv;
    __syncthreads();
    for (int k0 = 16; k0 <= K; k0 += 16) {
        bool more = (k0 < K);
        if (more) {
            av = *(const float4*)(pA + k0);
            bv = *(const float4*)(pB + (size_t)k0 * ldb);
        }
        float4 a_cur = *(const float4*)&As[buf][0][ty*4];
        float2 b_cur = *(const float2*)&Bs[buf][0][tx*2];
#pragma unroll
        for (int kk = 0; kk < 16; kk++) {
            float4 a_nxt = a_cur; float2 b_nxt = b_cur;
            if (kk < 15) {
                a_nxt = *(const float4*)&As[buf][kk+1][ty*4];
                b_nxt = *(const float2*)&Bs[buf][kk+1][tx*2];
            }
            microfma42(acc, a_cur, b_cur);
            a_cur = a_nxt; b_cur = b_nxt;
        }
        if (more) {
            int nb = buf ^ 1;
            As[nb][c4A+0][rowA]=av.x; As[nb][c4A+1][rowA]=av.y; As[nb][c4A+2][rowA]=av.z; As[nb][c4A+3][rowA]=av.w;
            *(float4*)&Bs[nb][kB][cB] = bv;
            __syncthreads();
            buf = nb;
        }
    }
}

// ---------------------------------------------------------------------------
// Projections + fused k/q row sums. grid (16, 32), 128 threads.
// bx: wsel = bx>>2, col tile = bx&3.  by: 32-row tile.
// ---------------------------------------------------------------------------
__global__ void __launch_bounds__(128) proj_kernel(
    const float* __restrict__ X,
    const float* __restrict__ Wk, const float* __restrict__ Wq,
    const float* __restrict__ Wv, const float* __restrict__ Ws,
    const float* __restrict__ bskip)
{
    __shared__ float As[2][16][32], Bs[2][16][64];
    __shared__ float red[32][17];
    int tid = threadIdx.x, tx = tid & 15, ty = tid >> 4;
    int bx = blockIdx.x, by = blockIdx.y;
    int wsel = bx >> 2;
    const float* W = (wsel == 0) ? Wk : (wsel == 1) ? Wq : (wsel == 2) ? Wv : Ws;
    int n0 = (bx & 3) * 64;
    int m0 = by * 32;
    float acc[4][4] = {};
    gemm_T3264(X, DD, m0, W, DD, n0, DD, acc, As, Bs, tid, tx, ty);

    float rs[4] = {0.f, 0.f, 0.f, 0.f};
#pragma unroll
    for (int i = 0; i < 4; i++) {
        int t = m0 + ty * 4 + i;
        float4 vs;
        float* vp = (float*)&vs;
#pragma unroll
        for (int j = 0; j < 4; j++) {
            int c = n0 + tx * 4 + j;
            float v = acc[i][j];
            if (wsel < 2) v = (v > 0.f) ? v : expm1f(v);
            if (wsel == 3) v += bskip[c];
            vp[j] = v;
            rs[i] += v;
        }
        *(float4*)&g_P[(size_t)t * LDP + wsel * 256 + n0 + tx * 4] = vs;
    }
    if (wsel < 2) {
        __syncthreads();
#pragma unroll
        for (int i = 0; i < 4; i++) red[ty * 4 + i][tx] = rs[i];
        __syncthreads();
        if (tid < 32) {
            float s = 0.f;
#pragma unroll
            for (int x = 0; x < 16; x++) s += red[tid][x];
            atomicAdd((wsel == 0) ? &g_ksum[m0 + tid] : &g_qsum[m0 + tid], s);
        }
    }
}

// ---------------------------------------------------------------------------
// denom[t] = qsum[t] * sum_j mask(t,j)*ksum[j].  ksum staged in SMEM.
// ---------------------------------------------------------------------------
__global__ void denom_kernel() {
    __shared__ float ks[1024];
    int tid = threadIdx.x;
    for (int i = tid; i < 1024; i += 256) ks[i] = g_ksum[i];
    __syncthreads();
    int row  = blockIdx.x * 8 + (tid >> 5);
    int lane = tid & 31;
    unsigned bits = g_M[row * 32 + lane];
    float s = 0.f;
    while (bits) {
        int b = __ffs(bits) - 1;
        bits &= bits - 1;
        s += ks[lane * 32 + b];
    }
#pragma unroll
    for (int o = 16; o > 0; o >>= 1) s += __shfl_xor_sync(0xffffffffu, s, o);
    if (lane == 0) g_den[row] = s * g_qsum[row];
}

// ---------------------------------------------------------------------------
// Masked scores: 32-row x 64-col lower-tri tiles -> 272 blocks, 128 threads.
// ---------------------------------------------------------------------------
__global__ void __launch_bounds__(128) scores_kernel() {
    int rem = blockIdx.x, bt = 0;
    while (rem >= (bt >> 1) + 1) { rem -= (bt >> 1) + 1; bt++; }
    int bi = rem;

    __shared__ float As[2][16][32], Bs[2][16][64];
    int tid = threadIdx.x, tx = tid & 15, ty = tid >> 4;
    float acc[4][4] = {};
    gemm_T3264(g_P + 256, LDP, bt * 32, g_P, LDP, bi * 64, DD, acc, As, Bs, tid, tx, ty);
#pragma unroll
    for (int i = 0; i < 4; i++) {
        int t = bt * 32 + ty * 4 + i;
        const unsigned* Mrow = &g_M[t * 32];
        float4 vs;
        float* vp = (float*)&vs;
#pragma unroll
        for (int j = 0; j < 4; j++) {
            int ki = bi * 64 + tx * 4 + j;
            unsigned bit = (Mrow[ki >> 5] >> (ki & 31)) & 1u;
            vp[j] = bit ? acc[i][j] : 0.f;
        }
        *(float4*)&g_A[(size_t)t * TT + bi * 64 + tx * 4] = vs;
    }
}

// ---------------------------------------------------------------------------
// numer = A @ V (K truncated at diagonal), / clipped denom.
// grid (8, 32), 128 threads, 32x32 tiles.
// ---------------------------------------------------------------------------
__global__ void __launch_bounds__(128) numer_kernel() {
    int bn = blockIdx.x, bt = blockIdx.y;
    __shared__ float As[2][16][32], Bs[2][16][32];
    int tid = threadIdx.x, tx = tid & 15, ty = tid >> 4;
    float acc[4][2] = {};
    int K = (bt + 1) * 32;
    gemm_N3232(g_A, TT, bt * 32, g_P + 512, LDP, bn * 32, K, acc, As, Bs, tid, tx, ty);
#pragma unroll
    for (int i = 0; i < 4; i++) {
        int t = bt * 32 + ty * 4 + i;
        float inv = 1.f / fmaxf(g_den[t], 1e-5f);
        float2 vs;
        vs.x = acc[i][0] * inv; vs.y = acc[i][1] * inv;
        *(float2*)&g_O[(size_t)t * HH + bn * 32 + tx * 2] = vs;
    }
}

// ---------------------------------------------------------------------------
// MLP GEMMs: grid (8, 32), 128 threads, 32x32 tiles.
// ---------------------------------------------------------------------------
__device__ __forceinline__ float mishf(float v) {
    float sp = (v > 20.f) ? v : log1pf(expf(v));
    return v * tanhf(sp);
}

template <int MODE>
__global__ void __launch_bounds__(128) mlp_kernel(const float* __restrict__ W,
                                                  const float* __restrict__ bias) {
    int bn = blockIdx.x, bm = blockIdx.y;
    __shared__ float As[2][16][32], Bs[2][16][32];
    int tid = threadIdx.x, tx = tid & 15, ty = tid >> 4;
    const float* Ain = (MODE == 0) ? g_O : (MODE == 1) ? g_H1 : g_H2;
    float* Cout = (MODE == 0) ? g_H1 : (MODE == 1) ? g_H2 : g_H3;
    float acc[4][2] = {};
    gemm_T3232(Ain, HH, bm * 32, W, HH, bn * 32, HH, acc, As, Bs, tid, tx, ty);
#pragma unroll
    for (int i = 0; i < 4; i++) {
        int t = bm * 32 + ty * 4 + i;
        float2 vs;
#pragma unroll
        for (int j = 0; j < 2; j++) {
            int c = bn * 32 + tx * 2 + j;
            float v = acc[i][j] + bias[c];
            if (MODE < 2) v = mishf(v);
            else          v += g_P[(size_t)t * LDP + 768 + c];
            ((float*)&vs)[j] = v;
        }
        *(float2*)&Cout[(size_t)t * HH + bn * 32 + tx * 2] = vs;
    }
}

// ---------------------------------------------------------------------------
// Per-row LayerNorm
// ---------------------------------------------------------------------------
__global__ void ln_kernel(const float* __restrict__ w, const float* __restrict__ b,
                          float* __restrict__ out) {
    int row = blockIdx.x, tid = threadIdx.x;
    float v = g_H3[(size_t)row * HH + tid];
    __shared__ float sh[8];
    float s = v;
#pragma unroll
    for (int o = 16; o > 0; o >>= 1) s += __shfl_xor_sync(0xffffffffu, s, o);
    if ((tid & 31) == 0) sh[tid >> 5] = s;
    __syncthreads();
    float tot = 0.f;
#pragma unroll
    for (int i = 0; i < 8; i++) tot += sh[i];
    float mean = tot * (1.f / 256.f);
    float d = v - mean;
    float s2 = d * d;
#pragma unroll
    for (int o = 16; o > 0; o >>= 1) s2 += __shfl_xor_sync(0xffffffffu, s2, o);
    __syncthreads();
    if ((tid & 31) == 0) sh[tid >> 5] = s2;
    __syncthreads();
    float tot2 = 0.f;
#pragma unroll
    for (int i = 0; i < 8; i++) tot2 += sh[i];
    float var = tot2 * (1.f / 256.f);
    out[(size_t)row * HH + tid] = d * rsqrtf(var + 1e-5f) * w[tid] + b[tid];
}

// ---------------------------------------------------------------------------
extern "C" void kernel_launch(void* const* d_in, const int* in_sizes, int n_in,
                              void* d_out, int out_size) {
    const float* x     = (const float*)d_in[0];
    const int*   start = (const int*)d_in[3];
    const int*   done  = (const int*)d_in[4];
    const float* Wk = (const float*)d_in[5];
    const float* Wq = (const float*)d_in[6];
    const float* Wv = (const float*)d_in[7];
    const float* Ws = (const float*)d_in[8];
    const float* bskip = (const float*)d_in[9];
    const float* W1 = (const float*)d_in[10];
    const float* b1 = (const float*)d_in[11];
    const float* W2 = (const float*)d_in[12];
    const float* b2 = (const float*)d_in[13];
    const float* W3 = (const float*)d_in[14];
    const float* b3 = (const float*)d_in[15];
    const float* lnw = (const float*)d_in[16];
    const float* lnb = (const float*)d_in[17];
    float* out = (float*)d_out;

    scan_mask_kernel<<<1, 1024>>>(start, done);
    proj_kernel<<<dim3(16, 32), 128>>>(x, Wk, Wq, Wv, Ws, bskip);
    denom_kernel<<<128, 256>>>();
    scores_kernel<<<272, 128>>>();
    numer_kernel<<<dim3(8, 32), 128>>>();
    mlp_kernel<0><<<dim3(8, 32), 128>>>(W1, b1);
    mlp_kernel<1><<<dim3(8, 32), 128>>>(W2, b2);
    mlp_kernel<2><<<dim3(8, 32), 128>>>(W3, b3);
    ln_kernel<<<1024, 256>>>(lnw, lnb, out);
}

// round 14
// speedup vs baseline: 2.4709x; 1.0439x over previous
#include <cuda_runtime.h>
#include <math.h>

#define TT   1024
#define DD   256
#define HH   256
#define LDP  1024

// ---------------- persistent scratch ----------------
__device__ float    g_P[TT*LDP];    // [0,256)=k(elu) [256,512)=q(elu) [512,768)=v [768,1024)=skip
__device__ float    g_As[2][TT*TT]; // unmasked score partials (lower-tri tiles)
__device__ float    g_Oc[4][TT*HH]; // numer chunk partials
__device__ float    g_R0a[TT*HH], g_R0b[TT*HH];  // mlp0 raw partials
__device__ float    g_R1a[TT*HH], g_R1b[TT*HH];  // mlp1 raw partials
__device__ float    g_R2a[TT*HH], g_R2b[TT*HH];  // mlp2 raw partials
__device__ unsigned g_M[TT*32];
__device__ float    g_den[TT], g_inv[TT];
__device__ float    g_ksum[TT], g_qsum[TT];
__device__ unsigned g_Dm[2048*32];
__device__ unsigned g_Sm[2048*32];
__device__ int      g_Dg[2048];

// ---------------------------------------------------------------------------
// Exact simulation of jax.lax.associative_scan bracketing on 1024-bit masks.
// ---------------------------------------------------------------------------
__global__ void scan_mask_kernel(const int* __restrict__ start, const int* __restrict__ done) {
    const int n[11]   = {1025,512,256,128,64,32,16,8,4,2,1};
    const int off[11] = {0,1025,1537,1793,1921,1985,2017,2033,2041,2045,2047};
    int tid = threadIdx.x;

    if (tid < 1024) { g_ksum[tid] = 0.f; g_qsum[tid] = 0.f; }

    for (int idx = tid; idx < 1025*32; idx += blockDim.x) {
        int i = idx >> 5, w = idx & 31;
        unsigned m = 0;
        if (i > 0 && ((i-1) >> 5) == w) m = 1u << ((i-1) & 31);
        g_Dm[idx] = m;
        if (w == 0) g_Dg[i] = (start[i] ? 1 : 0) | (done[i] ? 2 : 0);
    }
    __syncthreads();

    for (int d = 0; d < 10; d++) {
        int nn = n[d+1];
        int src = off[d], dst = off[d+1];
        for (int idx = tid; idx < nn*32; idx += blockDim.x) {
            int i = idx >> 5, w = idx & 31;
            int gb = g_Dg[src + 2*i + 1];
            unsigned m = 0;
            if (gb & 1) m |= g_Dm[(src + 2*i    )*32 + w];
            if (gb & 2) m |= g_Dm[(src + 2*i + 1)*32 + w];
            g_Dm[(dst + i)*32 + w] = m;
            if (w == 0) g_Dg[dst + i] = gb;
        }
        __syncthreads();
    }

    for (int w = tid; w < 32; w += blockDim.x)
        g_Sm[off[10]*32 + w] = g_Dm[off[10]*32 + w];
    __syncthreads();

    for (int d = 9; d >= 0; d--) {
        int nd = n[d];
        int src = off[d], o = off[d+1];
        for (int idx = tid; idx < nd*32; idx += blockDim.x) {
            int pos = idx >> 5, w = idx & 31;
            unsigned m;
            if (pos == 0) {
                m = g_Dm[src*32 + w];
            } else if (pos & 1) {
                m = g_Sm[(o + (pos >> 1))*32 + w];
            } else {
                int i = (pos >> 1) - 1;
                int gb = g_Dg[src + pos];
                m = 0;
                if (gb & 1) m |= g_Sm[(o + i)*32 + w];
                if (gb & 2) m |= g_Dm[(src + pos)*32 + w];
            }
            g_Sm[(src + pos)*32 + w] = m;
        }
        __syncthreads();
    }

    for (int idx = tid; idx < 1024*32; idx += blockDim.x) {
        int t = idx >> 5, w = idx & 31;
        g_M[idx] = g_Sm[(t + 1)*32 + w];
    }
}

// ---------------------------------------------------------------------------
// fp32 microkernels (proven R11)
// ---------------------------------------------------------------------------
__device__ __forceinline__ void microfma44(float acc[4][4], float4 a, float4 b) {
    acc[0][0] += a.x*b.x; acc[0][1] += a.x*b.y; acc[0][2] += a.x*b.z; acc[0][3] += a.x*b.w;
    acc[1][0] += a.y*b.x; acc[1][1] += a.y*b.y; acc[1][2] += a.y*b.z; acc[1][3] += a.y*b.w;
    acc[2][0] += a.z*b.x; acc[2][1] += a.z*b.y; acc[2][2] += a.z*b.z; acc[2][3] += a.z*b.w;
    acc[3][0] += a.w*b.x; acc[3][1] += a.w*b.y; acc[3][2] += a.w*b.z; acc[3][3] += a.w*b.w;
}
__device__ __forceinline__ void microfma42(float acc[4][2], float4 a, float2 b) {
    acc[0][0] += a.x*b.x; acc[0][1] += a.x*b.y;
    acc[1][0] += a.y*b.x; acc[1][1] += a.y*b.y;
    acc[2][0] += a.z*b.x; acc[2][1] += a.z*b.y;
    acc[3][0] += a.w*b.x; acc[3][1] += a.w*b.y;
}
__device__ __forceinline__ float mishf(float v) {
    float sp = (v > 20.f) ? v : log1pf(expf(v));
    return v * tanhf(sp);
}

// C[32x64] = A[32xK] * B[64xK]^T  (both k-contiguous rows). 128 threads.
__device__ __forceinline__ void gemm_T3264(
    const float* __restrict__ A, int lda, int m0,
    const float* __restrict__ B, int ldb, int n0,
    int K, float acc[4][4],
    float (*As)[16][32], float (*Bs)[16][64],
    int tid, int tx, int ty)
{
    int rowA = tid >> 2, c4A = (tid & 3) << 2;
    int rowB = tid >> 1, c8B = (tid & 1) << 3;
    const float* pA = A + (size_t)(m0 + rowA) * lda + c4A;
    const float* pB = B + (size_t)(n0 + rowB) * ldb + c8B;
    float4 av = *(const float4*)pA;
    float4 bv0 = *(const float4*)pB;
    float4 bv1 = *(const float4*)(pB + 4);
    int buf = 0;
    As[0][c4A+0][rowA]=av.x; As[0][c4A+1][rowA]=av.y; As[0][c4A+2][rowA]=av.z; As[0][c4A+3][rowA]=av.w;
    Bs[0][c8B+0][rowB]=bv0.x; Bs[0][c8B+1][rowB]=bv0.y; Bs[0][c8B+2][rowB]=bv0.z; Bs[0][c8B+3][rowB]=bv0.w;
    Bs[0][c8B+4][rowB]=bv1.x; Bs[0][c8B+5][rowB]=bv1.y; Bs[0][c8B+6][rowB]=bv1.z; Bs[0][c8B+7][rowB]=bv1.w;
    __syncthreads();
    for (int k0 = 16; k0 <= K; k0 += 16) {
        bool more = (k0 < K);
        if (more) {
            av  = *(const float4*)(pA + k0);
            bv0 = *(const float4*)(pB + k0);
            bv1 = *(const float4*)(pB + k0 + 4);
        }
        float4 a_cur = *(const float4*)&As[buf][0][ty*4];
        float4 b_cur = *(const float4*)&Bs[buf][0][tx*4];
#pragma unroll
        for (int kk = 0; kk < 16; kk++) {
            float4 a_nxt = a_cur, b_nxt = b_cur;
            if (kk < 15) {
                a_nxt = *(const float4*)&As[buf][kk+1][ty*4];
                b_nxt = *(const float4*)&Bs[buf][kk+1][tx*4];
            }
            microfma44(acc, a_cur, b_cur);
            a_cur = a_nxt; b_cur = b_nxt;
        }
        if (more) {
            int nb = buf ^ 1;
            As[nb][c4A+0][rowA]=av.x; As[nb][c4A+1][rowA]=av.y; As[nb][c4A+2][rowA]=av.z; As[nb][c4A+3][rowA]=av.w;
            Bs[nb][c8B+0][rowB]=bv0.x; Bs[nb][c8B+1][rowB]=bv0.y; Bs[nb][c8B+2][rowB]=bv0.z; Bs[nb][c8B+3][rowB]=bv0.w;
            Bs[nb][c8B+4][rowB]=bv1.x; Bs[nb][c8B+5][rowB]=bv1.y; Bs[nb][c8B+6][rowB]=bv1.z; Bs[nb][c8B+7][rowB]=bv1.w;
            __syncthreads();
            buf = nb;
        }
    }
}

// ---------------------------------------------------------------------------
// Projections + fused k/q row sums. grid (16, 32), 128 threads. (R11)
// ---------------------------------------------------------------------------
__global__ void __launch_bounds__(128) proj_kernel(
    const float* __restrict__ X,
    const float* __restrict__ Wk, const float* __restrict__ Wq,
    const float* __restrict__ Wv, const float* __restrict__ Ws,
    const float* __restrict__ bskip)
{
    __shared__ float As[2][16][32], Bs[2][16][64];
    __shared__ float red[32][17];
    int tid = threadIdx.x, tx = tid & 15, ty = tid >> 4;
    int bx = blockIdx.x, by = blockIdx.y;
    int wsel = bx >> 2;
    const float* W = (wsel == 0) ? Wk : (wsel == 1) ? Wq : (wsel == 2) ? Wv : Ws;
    int n0 = (bx & 3) * 64;
    int m0 = by * 32;
    float acc[4][4] = {};
    gemm_T3264(X, DD, m0, W, DD, n0, DD, acc, As, Bs, tid, tx, ty);

    float rs[4] = {0.f, 0.f, 0.f, 0.f};
#pragma unroll
    for (int i = 0; i < 4; i++) {
        int t = m0 + ty * 4 + i;
        float4 vs;
        float* vp = (float*)&vs;
#pragma unroll
        for (int j = 0; j < 4; j++) {
            int c = n0 + tx * 4 + j;
            float v = acc[i][j];
            if (wsel < 2) v = (v > 0.f) ? v : expm1f(v);
            if (wsel == 3) v += bskip[c];
            vp[j] = v;
            rs[i] += v;
        }
        *(float4*)&g_P[(size_t)t * LDP + wsel * 256 + n0 + tx * 4] = vs;
    }
    if (wsel < 2) {
        __syncthreads();
#pragma unroll
        for (int i = 0; i < 4; i++) red[ty * 4 + i][tx] = rs[i];
        __syncthreads();
        if (tid < 32) {
            float s = 0.f;
#pragma unroll
            for (int x = 0; x < 16; x++) s += red[tid][x];
            atomicAdd((wsel == 0) ? &g_ksum[m0 + tid] : &g_qsum[m0 + tid], s);
        }
    }
}

// ---------------------------------------------------------------------------
// denom[t] = qsum[t] * sum_j mask(t,j)*ksum[j];  g_inv = 1/clip(denom)
// ---------------------------------------------------------------------------
__global__ void denom_kernel() {
    __shared__ float ks[1024];
    int tid = threadIdx.x;
    for (int i = tid; i < 1024; i += 256) ks[i] = g_ksum[i];
    __syncthreads();
    int row  = blockIdx.x * 8 + (tid >> 5);
    int lane = tid & 31;
    unsigned bits = g_M[row * 32 + lane];
    float s = 0.f;
    while (bits) {
        int b = __ffs(bits) - 1;
        bits &= bits - 1;
        s += ks[lane * 32 + b];
    }
#pragma unroll
    for (int o = 16; o > 0; o >>= 1) s += __shfl_xor_sync(0xffffffffu, s, o);
    if (lane == 0) {
        float d = s * g_qsum[row];
        g_den[row] = d;
        g_inv[row] = 1.f / fmaxf(d, 1e-5f);
    }
}

// ---------------------------------------------------------------------------
// Scores (split-K2): grid (272 lower-tri 32x64 tiles, 2 K-halves).
// Unmasked partials -> g_As[ks]. 128 threads.
// ---------------------------------------------------------------------------
__global__ void __launch_bounds__(128) scores_kernel() {
    int rem = blockIdx.x, bt = 0;
    while (rem >= (bt >> 1) + 1) { rem -= (bt >> 1) + 1; bt++; }
    int bi = rem;
    int ks = blockIdx.y;

    __shared__ float As[2][16][32], Bs[2][16][64];
    int tid = threadIdx.x, tx = tid & 15, ty = tid >> 4;
    float acc[4][4] = {};
    gemm_T3264(g_P + 256 + ks * 128, LDP, bt * 32,
               g_P + ks * 128,       LDP, bi * 64, 128, acc, As, Bs, tid, tx, ty);

    float* out = g_As[ks];
#pragma unroll
    for (int i = 0; i < 4; i++) {
        int t = bt * 32 + ty * 4 + i;
        float4 vs;
        vs.x = acc[i][0]; vs.y = acc[i][1]; vs.z = acc[i][2]; vs.w = acc[i][3];
        *(float4*)&out[(size_t)t * TT + bi * 64 + tx * 4] = vs;
    }
}

// ---------------------------------------------------------------------------
// numer: grid (8 bn, 32 bt, 4 kc). Uniform K chunks (<=256), masked A-load
// summing both score halves. Partial output -> g_Oc[kc]. 128 threads.
// ---------------------------------------------------------------------------
__global__ void __launch_bounds__(128) numer_kernel() {
    int bn = blockIdx.x, bt = blockIdx.y, kc = blockIdx.z;
    int Krow = (bt + 1) * 32;
    if (kc * 256 >= Krow) return;
    int K = min(256, Krow - kc * 256);

    __shared__ float As[2][16][32], Bs[2][16][32];
    int tid = threadIdx.x, tx = tid & 15, ty = tid >> 4;

    int rowA = tid >> 2, c4A = (tid & 3) << 2;
    int kB = tid >> 3, cB = (tid & 7) << 2;
    int tg = bt * 32 + rowA;
    int kgb = kc * 256 + c4A;
    const float* A0 = g_As[0] + (size_t)tg * TT;
    const float* A1 = g_As[1] + (size_t)tg * TT;
    const unsigned* Mrow = &g_M[tg * 32];
    const float* pB = g_P + 512 + (size_t)(kc * 256 + kB) * LDP + bn * 32 + cB;

    float acc[4][2] = {};
    float4 av; float4 bv;

    auto fetchA = [&](int k0) {
        int kg = kgb + k0;
        float4 a0 = *(const float4*)&A0[kg];
        float4 a1 = *(const float4*)&A1[kg];
        unsigned w = Mrow[kg >> 5] >> (kg & 31);
        av.x = (w & 1u) ? a0.x + a1.x : 0.f;
        av.y = (w & 2u) ? a0.y + a1.y : 0.f;
        av.z = (w & 4u) ? a0.z + a1.z : 0.f;
        av.w = (w & 8u) ? a0.w + a1.w : 0.f;
    };

    fetchA(0);
    bv = *(const float4*)pB;
    int buf = 0;
    As[0][c4A+0][rowA]=av.x; As[0][c4A+1][rowA]=av.y; As[0][c4A+2][rowA]=av.z; As[0][c4A+3][rowA]=av.w;
    *(float4*)&Bs[0][kB][cB] = bv;
    __syncthreads();
    for (int k0 = 16; k0 <= K; k0 += 16) {
        bool more = (k0 < K);
        if (more) {
            fetchA(k0);
            bv = *(const float4*)(pB + (size_t)k0 * LDP);
        }
        float4 a_cur = *(const float4*)&As[buf][0][ty*4];
        float2 b_cur = *(const float2*)&Bs[buf][0][tx*2];
#pragma unroll
        for (int kk = 0; kk < 16; kk++) {
            float4 a_nxt = a_cur; float2 b_nxt = b_cur;
            if (kk < 15) {
                a_nxt = *(const float4*)&As[buf][kk+1][ty*4];
                b_nxt = *(const float2*)&Bs[buf][kk+1][tx*2];
            }
            microfma42(acc, a_cur, b_cur);
            a_cur = a_nxt; b_cur = b_nxt;
        }
        if (more) {
            int nb = buf ^ 1;
            As[nb][c4A+0][rowA]=av.x; As[nb][c4A+1][rowA]=av.y; As[nb][c4A+2][rowA]=av.z; As[nb][c4A+3][rowA]=av.w;
            *(float4*)&Bs[nb][kB][cB] = bv;
            __syncthreads();
            buf = nb;
        }
    }

    float* out = g_Oc[kc];
#pragma unroll
    for (int i = 0; i < 4; i++) {
        int t = bt * 32 + ty * 4 + i;
        float2 vs;
        vs.x = acc[i][0]; vs.y = acc[i][1];
        *(float2*)&out[(size_t)t * HH + bn * 32 + tx * 2] = vs;
    }
}

// ---------------------------------------------------------------------------
// MLP (split-K2): grid (8 bn, 32 bm, 2 kc), 128 threads, raw partials out.
// MODE 0: A = (sum chunks of g_Oc) * g_inv           -> g_R0{a,b}
// MODE 1: A = mish(g_R0a+g_R0b + b1)                 -> g_R1{a,b}
// MODE 2: A = mish(g_R1a+g_R1b + b2)                 -> g_R2{a,b}
// ---------------------------------------------------------------------------
template <int MODE>
__global__ void __launch_bounds__(128) mlp_kernel(const float* __restrict__ W,
                                                  const float* __restrict__ biasA) {
    int bn = blockIdx.x, bm = blockIdx.y, kc = blockIdx.z;
    __shared__ float As[2][16][32], Bs[2][16][32];
    int tid = threadIdx.x, tx = tid & 15, ty = tid >> 4;

    int rowA = tid >> 2, c4 = (tid & 3) << 2;
    int tg = bm * 32 + rowA;
    int kbase = kc * 128;
    int cmax = bm >> 3;   // MODE 0: number of extra numer chunks for this row tile
    const float* pB = W + (size_t)(bn * 32 + rowA) * HH + kbase + c4;

    float acc[4][2] = {};
    float4 av, bv;

    auto fetchA = [&](int k0) {
        int kg = kbase + k0 + c4;
        size_t idx = (size_t)tg * HH + kg;
        if (MODE == 0) {
            float4 s = *(const float4*)&g_Oc[0][idx];
#pragma unroll
            for (int c = 1; c < 4; c++) {
                if (c <= cmax) {
                    float4 u = *(const float4*)&g_Oc[c][idx];
                    s.x += u.x; s.y += u.y; s.z += u.z; s.w += u.w;
                }
            }
            float inv = g_inv[tg];
            av.x = s.x * inv; av.y = s.y * inv; av.z = s.z * inv; av.w = s.w * inv;
        } else {
            const float* Ra = (MODE == 1) ? g_R0a : g_R1a;
            const float* Rb = (MODE == 1) ? g_R0b : g_R1b;
            float4 a = *(const float4*)&Ra[idx];
            float4 b = *(const float4*)&Rb[idx];
            av.x = mishf(a.x + b.x + biasA[kg]);
            av.y = mishf(a.y + b.y + biasA[kg+1]);
            av.z = mishf(a.z + b.z + biasA[kg+2]);
            av.w = mishf(a.w + b.w + biasA[kg+3]);
        }
    };

    fetchA(0);
    bv = *(const float4*)pB;
    int buf = 0;
    As[0][c4+0][rowA]=av.x; As[0][c4+1][rowA]=av.y; As[0][c4+2][rowA]=av.z; As[0][c4+3][rowA]=av.w;
    Bs[0][c4+0][rowA]=bv.x; Bs[0][c4+1][rowA]=bv.y; Bs[0][c4+2][rowA]=bv.z; Bs[0][c4+3][rowA]=bv.w;
    __syncthreads();
    for (int k0 = 16; k0 <= 128; k0 += 16) {
        bool more = (k0 < 128);
        if (more) { fetchA(k0); bv = *(const float4*)(pB + k0); }
        float4 a_cur = *(const float4*)&As[buf][0][ty*4];
        float2 b_cur = *(const float2*)&Bs[buf][0][tx*2];
#pragma unroll
        for (int kk = 0; kk < 16; kk++) {
            float4 a_nxt = a_cur; float2 b_nxt = b_cur;
            if (kk < 15) {
                a_nxt = *(const float4*)&As[buf][kk+1][ty*4];
                b_nxt = *(const float2*)&Bs[buf][kk+1][tx*2];
            }
            microfma42(acc, a_cur, b_cur);
            a_cur = a_nxt; b_cur = b_nxt;
        }
        if (more) {
            int nb = buf ^ 1;
            As[nb][c4+0][rowA]=av.x; As[nb][c4+1][rowA]=av.y; As[nb][c4+2][rowA]=av.z; As[nb][c4+3][rowA]=av.w;
            Bs[nb][c4+0][rowA]=bv.x; Bs[nb][c4+1][rowA]=bv.y; Bs[nb][c4+2][rowA]=bv.z; Bs[nb][c4+3][rowA]=bv.w;
            __syncthreads();
            buf = nb;
        }
    }

    float* out = (MODE == 0) ? (kc ? g_R0b : g_R0a)
               : (MODE == 1) ? (kc ? g_R1b : g_R1a)
                             : (kc ? g_R2b : g_R2a);
#pragma unroll
    for (int i = 0; i < 4; i++) {
        int t = bm * 32 + ty * 4 + i;
        float2 vs;
        vs.x = acc[i][0]; vs.y = acc[i][1];
        *(float2*)&out[(size_t)t * HH + bn * 32 + tx * 2] = vs;
    }
}

// ---------------------------------------------------------------------------
// LayerNorm over h3 = (R2a + R2b + b3) + skip
// ---------------------------------------------------------------------------
__global__ void ln_kernel(const float* __restrict__ b3,
                          const float* __restrict__ w, const float* __restrict__ b,
                          float* __restrict__ out) {
    int row = blockIdx.x, tid = threadIdx.x;
    size_t idx = (size_t)row * HH + tid;
    float v = g_R2a[idx] + g_R2b[idx] + b3[tid] + g_P[(size_t)row * LDP + 768 + tid];
    __shared__ float sh[8];
    float s = v;
#pragma unroll
    for (int o = 16; o > 0; o >>= 1) s += __shfl_xor_sync(0xffffffffu, s, o);
    if ((tid & 31) == 0) sh[tid >> 5] = s;
    __syncthreads();
    float tot = 0.f;
#pragma unroll
    for (int i = 0; i < 8; i++) tot += sh[i];
    float mean = tot * (1.f / 256.f);
    float d = v - mean;
    float s2 = d * d;
#pragma unroll
    for (int o = 16; o > 0; o >>= 1) s2 += __shfl_xor_sync(0xffffffffu, s2, o);
    __syncthreads();
    if ((tid & 31) == 0) sh[tid >> 5] = s2;
    __syncthreads();
    float tot2 = 0.f;
#pragma unroll
    for (int i = 0; i < 8; i++) tot2 += sh[i];
    float var = tot2 * (1.f / 256.f);
    out[idx] = d * rsqrtf(var + 1e-5f) * w[tid] + b[tid];
}

// ---------------------------------------------------------------------------
extern "C" void kernel_launch(void* const* d_in, const int* in_sizes, int n_in,
                              void* d_out, int out_size) {
    const float* x     = (const float*)d_in[0];
    const int*   start = (const int*)d_in[3];
    const int*   done  = (const int*)d_in[4];
    const float* Wk = (const float*)d_in[5];
    const float* Wq = (const float*)d_in[6];
    const float* Wv = (const float*)d_in[7];
    const float* Ws = (const float*)d_in[8];
    const float* bskip = (const float*)d_in[9];
    const float* W1 = (const float*)d_in[10];
    const float* b1 = (const float*)d_in[11];
    const float* W2 = (const float*)d_in[12];
    const float* b2 = (const float*)d_in[13];
    const float* W3 = (const float*)d_in[14];
    const float* b3 = (const float*)d_in[15];
    const float* lnw = (const float*)d_in[16];
    const float* lnb = (const float*)d_in[17];
    float* out = (float*)d_out;

    scan_mask_kernel<<<1, 1024>>>(start, done);
    proj_kernel<<<dim3(16, 32), 128>>>(x, Wk, Wq, Wv, Ws, bskip);
    denom_kernel<<<128, 256>>>();
    scores_kernel<<<dim3(272, 2), 128>>>();
    numer_kernel<<<dim3(8, 32, 4), 128>>>();
    mlp_kernel<0><<<dim3(8, 32, 2), 128>>>(W1, nullptr);
    mlp_kernel<1><<<dim3(8, 32, 2), 128>>>(W2, b1);
    mlp_kernel<2><<<dim3(8, 32, 2), 128>>>(W3, b2);
    ln_kernel<<<1024, 256>>>(b3, lnw, lnb, out);
}

// round 15
// speedup vs baseline: 4.5349x; 1.8353x over previous
#include <cuda_runtime.h>
#include <math.h>

#define TT   1024
#define DD   256
#define HH   256
#define LDP  1024

// ---------------- persistent scratch ----------------
__device__ float    g_P[TT*LDP];    // [0,256)=k(elu) [256,512)=q(elu) [512,768)=v [768,1024)=skip
__device__ float    g_O[TT*HH];     // attention output (numer/denom)
__device__ float    g_R0a[TT*HH], g_R0b[TT*HH];  // mlp0 raw partials
__device__ float    g_R1a[TT*HH], g_R1b[TT*HH];  // mlp1 raw partials
__device__ float    g_R2a[TT*HH], g_R2b[TT*HH];  // mlp2 raw partials
__device__ unsigned g_M[TT*32];
__device__ float    g_ksum[TT], g_qsum[TT];

// ---------------------------------------------------------------------------
// Exact simulation of jax.lax.associative_scan bracketing on 1024-bit masks.
// Word-parallel: 32 blocks, block w handles bit-word w of every element, all
// in shared memory. Gates recomputed redundantly per block.
// ---------------------------------------------------------------------------
__global__ void __launch_bounds__(256) scan_mask_kernel(
    const int* __restrict__ start, const int* __restrict__ done)
{
    const int n[11]   = {1025,512,256,128,64,32,16,8,4,2,1};
    const int off[11] = {0,1025,1537,1793,1921,1985,2017,2033,2041,2045,2047};
    __shared__ unsigned Dm[2048], Sm[2048];
    __shared__ int      Gg[2048];
    int tid = threadIdx.x, w = blockIdx.x;

    if (w == 0) {
        for (int i = tid; i < 1024; i += 256) { g_ksum[i] = 0.f; g_qsum[i] = 0.f; }
    }
    for (int i = tid; i < 1025; i += 256) {
        unsigned m = 0;
        if (i > 0 && ((i - 1) >> 5) == w) m = 1u << ((i - 1) & 31);
        Dm[i] = m;
        Gg[i] = (start[i] ? 1 : 0) | (done[i] ? 2 : 0);
    }
    __syncthreads();

    // down-sweep: reduced[i] = combine(e[2i], e[2i+1])
    for (int d = 0; d < 10; d++) {
        int nn = n[d+1], src = off[d], dst = off[d+1];
        for (int i = tid; i < nn; i += 256) {
            int gb = Gg[src + 2*i + 1];
            unsigned m = 0;
            if (gb & 1) m |= Dm[src + 2*i];
            if (gb & 2) m |= Dm[src + 2*i + 1];
            Dm[dst + i] = m;
            Gg[dst + i] = gb;
        }
        __syncthreads();
    }

    if (tid == 0) Sm[off[10]] = Dm[off[10]];
    __syncthreads();

    // up-sweep
    for (int d = 9; d >= 0; d--) {
        int nd = n[d], src = off[d], o = off[d+1];
        for (int pos = tid; pos < nd; pos += 256) {
            unsigned m;
            if (pos == 0) {
                m = Dm[src];
            } else if (pos & 1) {
                m = Sm[o + (pos >> 1)];
            } else {
                int i = (pos >> 1) - 1;
                int gb = Gg[src + pos];
                m = 0;
                if (gb & 1) m |= Sm[o + i];
                if (gb & 2) m |= Dm[src + pos];
            }
            Sm[src + pos] = m;
        }
        __syncthreads();
    }

    for (int t = tid; t < 1024; t += 256)
        g_M[t * 32 + w] = Sm[t + 1];
}

// ---------------------------------------------------------------------------
// fp32 microkernels (proven R11/R14)
// ---------------------------------------------------------------------------
__device__ __forceinline__ void microfma44(float acc[4][4], float4 a, float4 b) {
    acc[0][0] += a.x*b.x; acc[0][1] += a.x*b.y; acc[0][2] += a.x*b.z; acc[0][3] += a.x*b.w;
    acc[1][0] += a.y*b.x; acc[1][1] += a.y*b.y; acc[1][2] += a.y*b.z; acc[1][3] += a.y*b.w;
    acc[2][0] += a.z*b.x; acc[2][1] += a.z*b.y; acc[2][2] += a.z*b.z; acc[2][3] += a.z*b.w;
    acc[3][0] += a.w*b.x; acc[3][1] += a.w*b.y; acc[3][2] += a.w*b.z; acc[3][3] += a.w*b.w;
}
__device__ __forceinline__ void microfma42(float acc[4][2], float4 a, float2 b) {
    acc[0][0] += a.x*b.x; acc[0][1] += a.x*b.y;
    acc[1][0] += a.y*b.x; acc[1][1] += a.y*b.y;
    acc[2][0] += a.z*b.x; acc[2][1] += a.z*b.y;
    acc[3][0] += a.w*b.x; acc[3][1] += a.w*b.y;
}
__device__ __forceinline__ float mishf(float v) {
    float sp = (v > 20.f) ? v : log1pf(expf(v));
    return v * tanhf(sp);
}

// C[32x64] = A[32xK] * B[64xK]^T  (both k-contiguous rows). 128 threads.
__device__ __forceinline__ void gemm_T3264(
    const float* __restrict__ A, int lda, int m0,
    const float* __restrict__ B, int ldb, int n0,
    int K, float acc[4][4],
    float (*As)[16][32], float (*Bs)[16][64],
    int tid, int tx, int ty)
{
    int rowA = tid >> 2, c4A = (tid & 3) << 2;
    int rowB = tid >> 1, c8B = (tid & 1) << 3;
    const float* pA = A + (size_t)(m0 + rowA) * lda + c4A;
    const float* pB = B + (size_t)(n0 + rowB) * ldb + c8B;
    float4 av = *(const float4*)pA;
    float4 bv0 = *(const float4*)pB;
    float4 bv1 = *(const float4*)(pB + 4);
    int buf = 0;
    As[0][c4A+0][rowA]=av.x; As[0][c4A+1][rowA]=av.y; As[0][c4A+2][rowA]=av.z; As[0][c4A+3][rowA]=av.w;
    Bs[0][c8B+0][rowB]=bv0.x; Bs[0][c8B+1][rowB]=bv0.y; Bs[0][c8B+2][rowB]=bv0.z; Bs[0][c8B+3][rowB]=bv0.w;
    Bs[0][c8B+4][rowB]=bv1.x; Bs[0][c8B+5][rowB]=bv1.y; Bs[0][c8B+6][rowB]=bv1.z; Bs[0][c8B+7][rowB]=bv1.w;
    __syncthreads();
    for (int k0 = 16; k0 <= K; k0 += 16) {
        bool more = (k0 < K);
        if (more) {
            av  = *(const float4*)(pA + k0);
            bv0 = *(const float4*)(pB + k0);
            bv1 = *(const float4*)(pB + k0 + 4);
        }
        float4 a_cur = *(const float4*)&As[buf][0][ty*4];
        float4 b_cur = *(const float4*)&Bs[buf][0][tx*4];
#pragma unroll
        for (int kk = 0; kk < 16; kk++) {
            float4 a_nxt = a_cur, b_nxt = b_cur;
            if (kk < 15) {
                a_nxt = *(const float4*)&As[buf][kk+1][ty*4];
                b_nxt = *(const float4*)&Bs[buf][kk+1][tx*4];
            }
            microfma44(acc, a_cur, b_cur);
            a_cur = a_nxt; b_cur = b_nxt;
        }
        if (more) {
            int nb = buf ^ 1;
            As[nb][c4A+0][rowA]=av.x; As[nb][c4A+1][rowA]=av.y; As[nb][c4A+2][rowA]=av.z; As[nb][c4A+3][rowA]=av.w;
            Bs[nb][c8B+0][rowB]=bv0.x; Bs[nb][c8B+1][rowB]=bv0.y; Bs[nb][c8B+2][rowB]=bv0.z; Bs[nb][c8B+3][rowB]=bv0.w;
            Bs[nb][c8B+4][rowB]=bv1.x; Bs[nb][c8B+5][rowB]=bv1.y; Bs[nb][c8B+6][rowB]=bv1.z; Bs[nb][c8B+7][rowB]=bv1.w;
            __syncthreads();
            buf = nb;
        }
    }
}

// ---------------------------------------------------------------------------
// Projections + fused k/q row sums. grid (16, 32), 128 threads. (R11)
// ---------------------------------------------------------------------------
__global__ void __launch_bounds__(128) proj_kernel(
    const float* __restrict__ X,
    const float* __restrict__ Wk, const float* __restrict__ Wq,
    const float* __restrict__ Wv, const float* __restrict__ Ws,
    const float* __restrict__ bskip)
{
    __shared__ float As[2][16][32], Bs[2][16][64];
    __shared__ float red[32][17];
    int tid = threadIdx.x, tx = tid & 15, ty = tid >> 4;
    int bx = blockIdx.x, by = blockIdx.y;
    int wsel = bx >> 2;
    const float* W = (wsel == 0) ? Wk : (wsel == 1) ? Wq : (wsel == 2) ? Wv : Ws;
    int n0 = (bx & 3) * 64;
    int m0 = by * 32;
    float acc[4][4] = {};
    gemm_T3264(X, DD, m0, W, DD, n0, DD, acc, As, Bs, tid, tx, ty);

    float rs[4] = {0.f, 0.f, 0.f, 0.f};
#pragma unroll
    for (int i = 0; i < 4; i++) {
        int t = m0 + ty * 4 + i;
        float4 vs;
        float* vp = (float*)&vs;
#pragma unroll
        for (int j = 0; j < 4; j++) {
            int c = n0 + tx * 4 + j;
            float v = acc[i][j];
            if (wsel < 2) v = (v > 0.f) ? v : expm1f(v);
            if (wsel == 3) v += bskip[c];
            vp[j] = v;
            rs[i] += v;
        }
        *(float4*)&g_P[(size_t)t * LDP + wsel * 256 + n0 + tx * 4] = vs;
    }
    if (wsel < 2) {
        __syncthreads();
#pragma unroll
        for (int i = 0; i < 4; i++) red[ty * 4 + i][tx] = rs[i];
        __syncthreads();
        if (tid < 32) {
            float s = 0.f;
#pragma unroll
            for (int x = 0; x < 16; x++) s += red[tid][x];
            atomicAdd((wsel == 0) ? &g_ksum[m0 + tid] : &g_qsum[m0 + tid], s);
        }
    }
}

// ---------------------------------------------------------------------------
// Sparse masked attention: one block per row t.
// out[t][c] = (sum_{j in mask(t)} (q_t . k_j) * v_j[c]) / clip(qsum_t * sum_j ksum_j)
// ---------------------------------------------------------------------------
__global__ void __launch_bounds__(256) attn_kernel() {
    __shared__ int   s_idx[1024];
    __shared__ float s_s[1024];
    __shared__ float red[8];
    __shared__ int   s_cnt;
    __shared__ float s_inv;
    int t = blockIdx.x, tid = threadIdx.x, lane = tid & 31, wid = tid >> 5;

    // enumerate set bits in ascending order (warp 0)
    if (tid < 32) {
        unsigned word = g_M[(size_t)t * 32 + tid];
        int pc = __popc(word);
        int inc = pc;
#pragma unroll
        for (int o = 1; o < 32; o <<= 1) {
            int v = __shfl_up_sync(0xffffffffu, inc, o);
            if (lane >= o) inc += v;
        }
        if (lane == 31) s_cnt = inc;
        int base = inc - pc;
        while (word) {
            int b = __ffs(word) - 1;
            word &= word - 1;
            s_idx[base++] = tid * 32 + b;
        }
    }
    __syncthreads();
    int nbits = s_cnt;

    // scores s_j = q_t . k_j  (8 warps over bits)
    const float* qrow = g_P + (size_t)t * LDP + 256;
    for (int i = wid; i < nbits; i += 8) {
        const float* krow = g_P + (size_t)s_idx[i] * LDP;
        float s = 0.f;
#pragma unroll
        for (int c = 0; c < 8; c++) s += qrow[lane + 32 * c] * krow[lane + 32 * c];
#pragma unroll
        for (int o = 16; o > 0; o >>= 1) s += __shfl_xor_sync(0xffffffffu, s, o);
        if (lane == 0) s_s[i] = s;
    }

    // denom = qsum_t * sum_j ksum_j
    float part = 0.f;
    for (int i = tid; i < nbits; i += 256) part += g_ksum[s_idx[i]];
#pragma unroll
    for (int o = 16; o > 0; o >>= 1) part += __shfl_xor_sync(0xffffffffu, part, o);
    if (lane == 0) red[wid] = part;
    __syncthreads();
    if (tid == 0) {
        float d = 0.f;
#pragma unroll
        for (int i = 0; i < 8; i++) d += red[i];
        d *= g_qsum[t];
        s_inv = 1.f / fmaxf(d, 1e-5f);
    }
    __syncthreads();

    // numer per column c = tid
    float inv = s_inv;
    float acc = 0.f;
    for (int i = 0; i < nbits; i++)
        acc += s_s[i] * g_P[(size_t)s_idx[i] * LDP + 512 + tid];
    g_O[(size_t)t * HH + tid] = acc * inv;
}

// ---------------------------------------------------------------------------
// MLP (split-K2): grid (8 bn, 32 bm, 2 kc), 128 threads, raw partials out.
// MODE 0: A = g_O                           -> g_R0{a,b}
// MODE 1: A = mish(g_R0a+g_R0b + b1)        -> g_R1{a,b}
// MODE 2: A = mish(g_R1a+g_R1b + b2)        -> g_R2{a,b}
// ---------------------------------------------------------------------------
template <int MODE>
__global__ void __launch_bounds__(128) mlp_kernel(const float* __restrict__ W,
                                                  const float* __restrict__ biasA) {
    int bn = blockIdx.x, bm = blockIdx.y, kc = blockIdx.z;
    __shared__ float As[2][16][32], Bs[2][16][32];
    int tid = threadIdx.x, tx = tid & 15, ty = tid >> 4;

    int rowA = tid >> 2, c4 = (tid & 3) << 2;
    int tg = bm * 32 + rowA;
    int kbase = kc * 128;
    const float* pB = W + (size_t)(bn * 32 + rowA) * HH + kbase + c4;

    float acc[4][2] = {};
    float4 av, bv;

    auto fetchA = [&](int k0) {
        int kg = kbase + k0 + c4;
        size_t idx = (size_t)tg * HH + kg;
        if (MODE == 0) {
            av = *(const float4*)&g_O[idx];
        } else {
            const float* Ra = (MODE == 1) ? g_R0a : g_R1a;
            const float* Rb = (MODE == 1) ? g_R0b : g_R1b;
            float4 a = *(const float4*)&Ra[idx];
            float4 b = *(const float4*)&Rb[idx];
            av.x = mishf(a.x + b.x + biasA[kg]);
            av.y = mishf(a.y + b.y + biasA[kg+1]);
            av.z = mishf(a.z + b.z + biasA[kg+2]);
            av.w = mishf(a.w + b.w + biasA[kg+3]);
        }
    };

    fetchA(0);
    bv = *(const float4*)pB;
    int buf = 0;
    As[0][c4+0][rowA]=av.x; As[0][c4+1][rowA]=av.y; As[0][c4+2][rowA]=av.z; As[0][c4+3][rowA]=av.w;
    Bs[0][c4+0][rowA]=bv.x; Bs[0][c4+1][rowA]=bv.y; Bs[0][c4+2][rowA]=bv.z; Bs[0][c4+3][rowA]=bv.w;
    __syncthreads();
    for (int k0 = 16; k0 <= 128; k0 += 16) {
        bool more = (k0 < 128);
        if (more) { fetchA(k0); bv = *(const float4*)(pB + k0); }
        float4 a_cur = *(const float4*)&As[buf][0][ty*4];
        float2 b_cur = *(const float2*)&Bs[buf][0][tx*2];
#pragma unroll
        for (int kk = 0; kk < 16; kk++) {
            float4 a_nxt = a_cur; float2 b_nxt = b_cur;
            if (kk < 15) {
                a_nxt = *(const float4*)&As[buf][kk+1][ty*4];
                b_nxt = *(const float2*)&Bs[buf][kk+1][tx*2];
            }
            microfma42(acc, a_cur, b_cur);
            a_cur = a_nxt; b_cur = b_nxt;
        }
        if (more) {
            int nb = buf ^ 1;
            As[nb][c4+0][rowA]=av.x; As[nb][c4+1][rowA]=av.y; As[nb][c4+2][rowA]=av.z; As[nb][c4+3][rowA]=av.w;
            Bs[nb][c4+0][rowA]=bv.x; Bs[nb][c4+1][rowA]=bv.y; Bs[nb][c4+2][rowA]=bv.z; Bs[nb][c4+3][rowA]=bv.w;
            __syncthreads();
            buf = nb;
        }
    }

    float* out = (MODE == 0) ? (kc ? g_R0b : g_R0a)
               : (MODE == 1) ? (kc ? g_R1b : g_R1a)
                             : (kc ? g_R2b : g_R2a);
#pragma unroll
    for (int i = 0; i < 4; i++) {
        int t = bm * 32 + ty * 4 + i;
        float2 vs;
        vs.x = acc[i][0]; vs.y = acc[i][1];
        *(float2*)&out[(size_t)t * HH + bn * 32 + tx * 2] = vs;
    }
}

// ---------------------------------------------------------------------------
// LayerNorm over h3 = (R2a + R2b + b3) + skip
// ---------------------------------------------------------------------------
__global__ void ln_kernel(const float* __restrict__ b3,
                          const float* __restrict__ w, const float* __restrict__ b,
                          float* __restrict__ out) {
    int row = blockIdx.x, tid = threadIdx.x;
    size_t idx = (size_t)row * HH + tid;
    float v = g_R2a[idx] + g_R2b[idx] + b3[tid] + g_P[(size_t)row * LDP + 768 + tid];
    __shared__ float sh[8];
    float s = v;
#pragma unroll
    for (int o = 16; o > 0; o >>= 1) s += __shfl_xor_sync(0xffffffffu, s, o);
    if ((tid & 31) == 0) sh[tid >> 5] = s;
    __syncthreads();
    float tot = 0.f;
#pragma unroll
    for (int i = 0; i < 8; i++) tot += sh[i];
    float mean = tot * (1.f / 256.f);
    float d = v - mean;
    float s2 = d * d;
#pragma unroll
    for (int o = 16; o > 0; o >>= 1) s2 += __shfl_xor_sync(0xffffffffu, s2, o);
    __syncthreads();
    if ((tid & 31) == 0) sh[tid >> 5] = s2;
    __syncthreads();
    float tot2 = 0.f;
#pragma unroll
    for (int i = 0; i < 8; i++) tot2 += sh[i];
    float var = tot2 * (1.f / 256.f);
    out[idx] = d * rsqrtf(var + 1e-5f) * w[tid] + b[tid];
}

// ---------------------------------------------------------------------------
extern "C" void kernel_launch(void* const* d_in, const int* in_sizes, int n_in,
                              void* d_out, int out_size) {
    const float* x     = (const float*)d_in[0];
    const int*   start = (const int*)d_in[3];
    const int*   done  = (const int*)d_in[4];
    const float* Wk = (const float*)d_in[5];
    const float* Wq = (const float*)d_in[6];
    const float* Wv = (const float*)d_in[7];
    const float* Ws = (const float*)d_in[8];
    const float* bskip = (const float*)d_in[9];
    const float* W1 = (const float*)d_in[10];
    const float* b1 = (const float*)d_in[11];
    const float* W2 = (const float*)d_in[12];
    const float* b2 = (const float*)d_in[13];
    const float* W3 = (const float*)d_in[14];
    const float* b3 = (const float*)d_in[15];
    const float* lnw = (const float*)d_in[16];
    const float* lnb = (const float*)d_in[17];
    float* out = (float*)d_out;

    scan_mask_kernel<<<32, 256>>>(start, done);
    proj_kernel<<<dim3(16, 32), 128>>>(x, Wk, Wq, Wv, Ws, bskip);
    attn_kernel<<<1024, 256>>>();
    mlp_kernel<0><<<dim3(8, 32, 2), 128>>>(W1, nullptr);
    mlp_kernel<1><<<dim3(8, 32, 2), 128>>>(W2, b1);
    mlp_kernel<2><<<dim3(8, 32, 2), 128>>>(W3, b2);
    ln_kernel<<<1024, 256>>>(b3, lnw, lnb, out);
}